// round 2
// baseline (speedup 1.0000x reference)
#include <cuda_runtime.h>
#include <math.h>

typedef unsigned long long ull;

// Problem constants (fixed shapes per reference)
constexpr int N_PTS   = 65536;
constexpr int N_NEIGH = 32;
constexpr int KP      = 15;
constexpr int IN_F    = 64;
constexpr int OUT_F   = 128;
constexpr int RDIM    = KP * IN_F;          // 960
constexpr float INV_EXT = 1.0f / 0.024f;    // 1 / (1.2*0.1/5)
constexpr float BN_EPS  = 1e-6f;
constexpr float NEG_SLOPE = 0.1f;

// Scratch (device globals: allocation-free per harness rules)
__device__ float g_P[(size_t)N_PTS * RDIM];     // 240 MB weighted features
__device__ float g_psum[256 * OUT_F];
__device__ float g_psq [256 * OUT_F];
__device__ float g_scale[OUT_F];
__device__ float g_bias [OUT_F];

// ---- packed f32x2 helpers (FFMA2: 2 FMAs per issue slot on sm_103a) ----
__device__ __forceinline__ ull pk2(float lo, float hi) {
    ull r; asm("mov.b64 %0, {%1, %2};" : "=l"(r) : "f"(lo), "f"(hi)); return r;
}
__device__ __forceinline__ void up2(ull v, float& lo, float& hi) {
    asm("mov.b64 {%0, %1}, %2;" : "=f"(lo), "=f"(hi) : "l"(v));
}
__device__ __forceinline__ ull fma2(ull a, ull b, ull c) {
    ull d; asm("fma.rn.f32x2 %0, %1, %2, %3;" : "=l"(d) : "l"(a), "l"(b), "l"(c));
    return d;
}

// =====================================================================
// K1: weighted[n, k, i] = sum_m max(0, 1 - |diff(n,m)-kp_k|/ext) * feat[nbr(n,m), i]
// CTA = 16 points x 16 lanes (each lane owns 4 contiguous i), 256 threads.
// =====================================================================
__global__ __launch_bounds__(256) void k1_weighted(
    const float* __restrict__ qp, const float* __restrict__ sp,
    const int*   __restrict__ nbr, const float* __restrict__ feat,
    const float* __restrict__ kpts)
{
    __shared__ float kp_s[16][3];
    __shared__ float qp_s[16][3];
    __shared__ int   nbr_s[16][32];
    __shared__ float w_s[16][32][16];   // K padded to 16 (slot 15 = 0)

    const int t = threadIdx.x;
    const int base = blockIdx.x * 16;

    if (t < 45) kp_s[t / 3][t % 3] = kpts[t];
    if (t >= 64 && t < 112) { int u = t - 64; qp_s[u / 3][u % 3] = qp[base * 3 + u]; }
    ((int*)nbr_s)[t]       = nbr[base * 32 + t];
    ((int*)nbr_s)[t + 256] = nbr[base * 32 + t + 256];
    __syncthreads();

    // Phase B: influence weights for 512 (pt, m) pairs
    #pragma unroll
    for (int pair = t; pair < 512; pair += 256) {
        const int pt = pair >> 5, m = pair & 31;
        const int j = nbr_s[pt][m];
        const float dx = sp[(size_t)j * 3 + 0] - qp_s[pt][0];
        const float dy = sp[(size_t)j * 3 + 1] - qp_s[pt][1];
        const float dz = sp[(size_t)j * 3 + 2] - qp_s[pt][2];
        #pragma unroll
        for (int k = 0; k < KP; k++) {
            const float ax = dx - kp_s[k][0];
            const float ay = dy - kp_s[k][1];
            const float az = dz - kp_s[k][2];
            const float sq = ax * ax + ay * ay + az * az;
            w_s[pt][m][k] = fmaxf(1.0f - sqrtf(sq) * INV_EXT, 0.0f);
        }
        w_s[pt][m][15] = 0.0f;
    }
    __syncthreads();

    // Phase C: accumulate weighted features; lane owns i in [lane*4, lane*4+4)
    const int pt = t >> 4, lane = t & 15;
    const int gpt = base + pt;

    ull acc0[KP], acc1[KP];
    #pragma unroll
    for (int k = 0; k < KP; k++) { acc0[k] = 0ull; acc1[k] = 0ull; }

    int j0 = nbr_s[pt][0];
    float4 f = __ldg(reinterpret_cast<const float4*>(feat + (size_t)j0 * IN_F) + lane);

    #pragma unroll 2
    for (int m = 0; m < 32; m++) {
        float4 fn = f;
        if (m < 31) {
            const int jn = nbr_s[pt][m + 1];
            fn = __ldg(reinterpret_cast<const float4*>(feat + (size_t)jn * IN_F) + lane);
        }
        const ull fxy = pk2(f.x, f.y);
        const ull fzw = pk2(f.z, f.w);
        const float* wrow = w_s[pt][m];
        #pragma unroll
        for (int k = 0; k < KP; k++) {
            const float w = wrow[k];
            const ull wp = pk2(w, w);
            acc0[k] = fma2(wp, fxy, acc0[k]);
            acc1[k] = fma2(wp, fzw, acc1[k]);
        }
        f = fn;
    }

    float* dst = g_P + (size_t)gpt * RDIM + lane * 4;
    #pragma unroll
    for (int k = 0; k < KP; k++) {
        float4 v;
        up2(acc0[k], v.x, v.y);
        up2(acc1[k], v.z, v.w);
        *reinterpret_cast<float4*>(dst + k * IN_F) = v;
    }
}

// =====================================================================
// K2: x[65536,128] = P[65536,960] @ Wf[960,128]  (fp32, FFMA2)
// CTA tile 128x128, K-step 16. 256 threads, each computes 8x8 outputs.
// =====================================================================
__global__ __launch_bounds__(256) void k2_gemm(
    const float* __restrict__ Wf, float* __restrict__ out)
{
    __shared__ float As[16][128];   // As[k][row]
    __shared__ float Bs[16][128];   // Bs[k][col]

    const int t = threadIdx.x;
    const int rowBase = blockIdx.x * 128;
    const int ty = t >> 4, tx = t & 15;

    ull acc[8][4];
    #pragma unroll
    for (int r = 0; r < 8; r++)
        #pragma unroll
        for (int c = 0; c < 4; c++) acc[r][c] = 0ull;

    for (int kk = 0; kk < RDIM; kk += 16) {
        // Load A tile (128 rows x 16 k), store transposed
        #pragma unroll
        for (int q = 0; q < 2; q++) {
            const int idx = t * 2 + q;
            const int row = idx >> 2, c4 = idx & 3;
            float4 v = *reinterpret_cast<const float4*>(
                g_P + (size_t)(rowBase + row) * RDIM + kk + c4 * 4);
            As[c4 * 4 + 0][row] = v.x;
            As[c4 * 4 + 1][row] = v.y;
            As[c4 * 4 + 2][row] = v.z;
            As[c4 * 4 + 3][row] = v.w;
        }
        // Load B tile (16 k x 128 cols), coalesced
        #pragma unroll
        for (int q = 0; q < 2; q++) {
            const int idx = t * 2 + q;
            const int r = idx >> 5, c4 = idx & 31;
            *reinterpret_cast<float4*>(&Bs[r][c4 * 4]) =
                *reinterpret_cast<const float4*>(Wf + (size_t)(kk + r) * OUT_F + c4 * 4);
        }
        __syncthreads();

        #pragma unroll
        for (int k = 0; k < 16; k++) {
            float a[8];
            #pragma unroll
            for (int r = 0; r < 8; r++) a[r] = As[k][ty * 8 + r];
            const float4 b0 = *reinterpret_cast<const float4*>(&Bs[k][tx * 8]);
            const float4 b1 = *reinterpret_cast<const float4*>(&Bs[k][tx * 8 + 4]);
            const ull bp[4] = { pk2(b0.x, b0.y), pk2(b0.z, b0.w),
                                pk2(b1.x, b1.y), pk2(b1.z, b1.w) };
            #pragma unroll
            for (int r = 0; r < 8; r++) {
                const ull ap = pk2(a[r], a[r]);
                #pragma unroll
                for (int c = 0; c < 4; c++) acc[r][c] = fma2(ap, bp[c], acc[r][c]);
            }
        }
        __syncthreads();
    }

    #pragma unroll
    for (int r = 0; r < 8; r++) {
        float4 v0, v1;
        up2(acc[r][0], v0.x, v0.y); up2(acc[r][1], v0.z, v0.w);
        up2(acc[r][2], v1.x, v1.y); up2(acc[r][3], v1.z, v1.w);
        float* o = out + (size_t)(rowBase + ty * 8 + r) * OUT_F + tx * 8;
        *reinterpret_cast<float4*>(o)     = v0;
        *reinterpret_cast<float4*>(o + 4) = v1;
    }
}

// =====================================================================
// K3a: per-block partial column sums / sumsq over 256-row slices
// =====================================================================
__global__ __launch_bounds__(256) void k3a_partial(const float* __restrict__ x)
{
    const int t = threadIdx.x;
    const int c = t & 127, h = t >> 7;
    float s = 0.0f, q = 0.0f;
    const size_t rowBase = (size_t)blockIdx.x * 256;
    for (int r = 0; r < 128; r++) {
        const float v = x[(rowBase + (size_t)r * 2 + h) * OUT_F + c];
        s += v;
        q = fmaf(v, v, q);
    }
    __shared__ float ss[256], sq[256];
    ss[t] = s; sq[t] = q;
    __syncthreads();
    if (t < 128) {
        g_psum[blockIdx.x * OUT_F + t] = ss[t] + ss[t + 128];
        g_psq [blockIdx.x * OUT_F + t] = sq[t] + sq[t + 128];
    }
}

// K3b: finalize mean/var -> scale/bias (1 CTA, 128 threads; deterministic)
__global__ void k3b_finalize(const float* __restrict__ gamma,
                             const float* __restrict__ beta)
{
    const int c = threadIdx.x;
    float s = 0.0f, q = 0.0f;
    for (int b = 0; b < 256; b++) {
        s += g_psum[b * OUT_F + c];
        q += g_psq [b * OUT_F + c];
    }
    const float inv_n = 1.0f / (float)N_PTS;
    const float mean = s * inv_n;
    const float var  = q * inv_n - mean * mean;
    const float sc   = gamma[c] * rsqrtf(var + BN_EPS);
    g_scale[c] = sc;
    g_bias[c]  = beta[c] - mean * sc;
}

// K4: in-place BN affine + LeakyReLU, float4-vectorized
__global__ __launch_bounds__(256) void k4_bnrelu(float* __restrict__ x)
{
    const int i = blockIdx.x * 256 + threadIdx.x;       // one float4 each
    float4 v = reinterpret_cast<float4*>(x)[i];
    const int c0 = (i * 4) & 127;
    const float4 sc = *reinterpret_cast<const float4*>(g_scale + c0);
    const float4 bi = *reinterpret_cast<const float4*>(g_bias + c0);
    v.x = fmaf(v.x, sc.x, bi.x); v.x = (v.x >= 0.0f) ? v.x : NEG_SLOPE * v.x;
    v.y = fmaf(v.y, sc.y, bi.y); v.y = (v.y >= 0.0f) ? v.y : NEG_SLOPE * v.y;
    v.z = fmaf(v.z, sc.z, bi.z); v.z = (v.z >= 0.0f) ? v.z : NEG_SLOPE * v.z;
    v.w = fmaf(v.w, sc.w, bi.w); v.w = (v.w >= 0.0f) ? v.w : NEG_SLOPE * v.w;
    reinterpret_cast<float4*>(x)[i] = v;
}

// =====================================================================
extern "C" void kernel_launch(void* const* d_in, const int* in_sizes, int n_in,
                              void* d_out, int out_size)
{
    const float* qp    = (const float*)d_in[0];   // query_points  [65536,3]
    const float* sp    = (const float*)d_in[1];   // support_points[65536,3]
    const int*   nbr   = (const int*)  d_in[2];   // neighbors     [65536,32]
    const float* feat  = (const float*)d_in[3];   // features      [65536,64]
    const float* kpts  = (const float*)d_in[4];   // kernel_points [15,3]
    const float* Wf    = (const float*)d_in[5];   // W             [15,64,128]
    const float* gamma = (const float*)d_in[6];   // [128]
    const float* beta  = (const float*)d_in[7];   // [128]
    float* out = (float*)d_out;                   // [65536,128]

    k1_weighted<<<N_PTS / 16, 256>>>(qp, sp, nbr, feat, kpts);
    k2_gemm<<<N_PTS / 128, 256>>>(Wf, out);
    k3a_partial<<<256, 256>>>(out);
    k3b_finalize<<<1, 128>>>(gamma, beta);
    k4_bnrelu<<<(N_PTS * OUT_F / 4) / 256, 256>>>(out);
}

// round 5
// speedup vs baseline: 1.6914x; 1.6914x over previous
#include <cuda_runtime.h>
#include <cuda_fp16.h>
#include <math.h>
#include <stdint.h>

typedef unsigned long long ull;

// Problem constants (fixed shapes per reference)
constexpr int N_PTS   = 65536;
constexpr int KP      = 15;
constexpr int IN_F    = 64;
constexpr int OUT_F   = 128;
constexpr int RDIM    = KP * IN_F;          // 960
constexpr float INV_EXT = 1.0f / 0.024f;    // 1 / (1.2*0.1/5)
constexpr float BN_EPS  = 1e-6f;
constexpr float NEG_SLOPE = 0.1f;

// Scratch (device globals: allocation-free per harness rules)
__device__ __half g_Ph[(size_t)N_PTS * RDIM];   // weighted features, fp16 hi
__device__ __half g_Pl[(size_t)N_PTS * RDIM];   // fp16 lo residual
__device__ __half g_Whh[(size_t)RDIM * OUT_F];  // W fp16 hi  [k][o]
__device__ __half g_Whl[(size_t)RDIM * OUT_F];  // W fp16 lo
__device__ float g_psum[256 * OUT_F];
__device__ float g_psq [256 * OUT_F];
__device__ float g_scale[OUT_F];
__device__ float g_bias [OUT_F];

// ---- packed f32x2 helpers (K1) ----
__device__ __forceinline__ ull pk2(float lo, float hi) {
    ull r; asm("mov.b64 %0, {%1, %2};" : "=l"(r) : "f"(lo), "f"(hi)); return r;
}
__device__ __forceinline__ void up2(ull v, float& lo, float& hi) {
    asm("mov.b64 {%0, %1}, %2;" : "=f"(lo), "=f"(hi) : "l"(v));
}
__device__ __forceinline__ ull fma2(ull a, ull b, ull c) {
    ull d; asm("fma.rn.f32x2 %0, %1, %2, %3;" : "=l"(d) : "l"(a), "l"(b), "l"(c));
    return d;
}

__device__ __forceinline__ uint32_t smem_u32(const void* p) {
    uint32_t a;
    asm("{ .reg .u64 t; cvta.to.shared.u64 t, %1; cvt.u32.u64 %0, t; }" : "=r"(a) : "l"(p));
    return a;
}

// ---- mma.sync helpers (sm_80+ generic, legal on compute_103 PTX) ----
__device__ __forceinline__ void ldmatrix_x4(uint32_t* r, uint32_t addr) {
    asm volatile("ldmatrix.sync.aligned.m8n8.x4.shared.b16 {%0,%1,%2,%3}, [%4];"
                 : "=r"(r[0]), "=r"(r[1]), "=r"(r[2]), "=r"(r[3]) : "r"(addr));
}
__device__ __forceinline__ void ldmatrix_x4_t(uint32_t* r, uint32_t addr) {
    asm volatile("ldmatrix.sync.aligned.m8n8.x4.trans.shared.b16 {%0,%1,%2,%3}, [%4];"
                 : "=r"(r[0]), "=r"(r[1]), "=r"(r[2]), "=r"(r[3]) : "r"(addr));
}
__device__ __forceinline__ void mma16816(float* c, const uint32_t* a,
                                         const uint32_t* b) {
    asm volatile(
        "mma.sync.aligned.m16n8k16.row.col.f32.f16.f16.f32 "
        "{%0,%1,%2,%3}, {%4,%5,%6,%7}, {%8,%9}, {%0,%1,%2,%3};"
        : "+f"(c[0]), "+f"(c[1]), "+f"(c[2]), "+f"(c[3])
        : "r"(a[0]), "r"(a[1]), "r"(a[2]), "r"(a[3]), "r"(b[0]), "r"(b[1]));
}

// =====================================================================
// K0: split W[k][o] -> fp16 hi/lo
// =====================================================================
__global__ __launch_bounds__(256) void k0_prep(const float* __restrict__ W) {
    const int idx = blockIdx.x * 256 + threadIdx.x;
    if (idx >= RDIM * OUT_F) return;
    const float w = W[idx];
    const __half hi = __float2half_rn(w);
    g_Whh[idx] = hi;
    g_Whl[idx] = __float2half_rn(w - __half2float(hi));
}

// =====================================================================
// K1: weighted[n,k,i] = sum_m max(0, 1-|diff-kp_k|/ext) * feat[nbr,i]
// Emits fp16 hi/lo split directly.
// =====================================================================
__global__ __launch_bounds__(256) void k1_weighted(
    const float* __restrict__ qp, const float* __restrict__ sp,
    const int*   __restrict__ nbr, const float* __restrict__ feat,
    const float* __restrict__ kpts)
{
    __shared__ float kp_s[16][3];
    __shared__ float qp_s[16][3];
    __shared__ int   nbr_s[16][32];
    __shared__ float w_s[16][32][16];

    const int t = threadIdx.x;
    const int base = blockIdx.x * 16;

    if (t < 45) kp_s[t / 3][t % 3] = kpts[t];
    if (t >= 64 && t < 112) { int u = t - 64; qp_s[u / 3][u % 3] = qp[base * 3 + u]; }
    ((int*)nbr_s)[t]       = nbr[base * 32 + t];
    ((int*)nbr_s)[t + 256] = nbr[base * 32 + t + 256];
    __syncthreads();

    #pragma unroll
    for (int pair = t; pair < 512; pair += 256) {
        const int pt = pair >> 5, m = pair & 31;
        const int j = nbr_s[pt][m];
        const float dx = sp[(size_t)j * 3 + 0] - qp_s[pt][0];
        const float dy = sp[(size_t)j * 3 + 1] - qp_s[pt][1];
        const float dz = sp[(size_t)j * 3 + 2] - qp_s[pt][2];
        #pragma unroll
        for (int k = 0; k < KP; k++) {
            const float ax = dx - kp_s[k][0];
            const float ay = dy - kp_s[k][1];
            const float az = dz - kp_s[k][2];
            const float sq = ax * ax + ay * ay + az * az;
            w_s[pt][m][k] = fmaxf(1.0f - sqrtf(sq) * INV_EXT, 0.0f);
        }
        w_s[pt][m][15] = 0.0f;
    }
    __syncthreads();

    const int pt = t >> 4, lane = t & 15;
    const int gpt = base + pt;

    ull acc0[KP], acc1[KP];
    #pragma unroll
    for (int k = 0; k < KP; k++) { acc0[k] = 0ull; acc1[k] = 0ull; }

    int j0 = nbr_s[pt][0];
    float4 f = __ldg(reinterpret_cast<const float4*>(feat + (size_t)j0 * IN_F) + lane);

    #pragma unroll 2
    for (int m = 0; m < 32; m++) {
        float4 fn = f;
        if (m < 31) {
            const int jn = nbr_s[pt][m + 1];
            fn = __ldg(reinterpret_cast<const float4*>(feat + (size_t)jn * IN_F) + lane);
        }
        const ull fxy = pk2(f.x, f.y);
        const ull fzw = pk2(f.z, f.w);
        const float* wrow = w_s[pt][m];
        #pragma unroll
        for (int k = 0; k < KP; k++) {
            const float w = wrow[k];
            const ull wp = pk2(w, w);
            acc0[k] = fma2(wp, fxy, acc0[k]);
            acc1[k] = fma2(wp, fzw, acc1[k]);
        }
        f = fn;
    }

    const size_t rbase = (size_t)gpt * RDIM + lane * 4;
    #pragma unroll
    for (int k = 0; k < KP; k++) {
        float vx, vy, vz, vw;
        up2(acc0[k], vx, vy);
        up2(acc1[k], vz, vw);
        const __half hx = __float2half_rn(vx), hy = __float2half_rn(vy);
        const __half hz = __float2half_rn(vz), hw = __float2half_rn(vw);
        const __half lx = __float2half_rn(vx - __half2float(hx));
        const __half ly = __float2half_rn(vy - __half2float(hy));
        const __half lz = __float2half_rn(vz - __half2float(hz));
        const __half lw = __float2half_rn(vw - __half2float(hw));
        __half2* ph = reinterpret_cast<__half2*>(g_Ph + rbase + k * IN_F);
        __half2* pl = reinterpret_cast<__half2*>(g_Pl + rbase + k * IN_F);
        ph[0] = __halves2half2(hx, hy); ph[1] = __halves2half2(hz, hw);
        pl[0] = __halves2half2(lx, ly); pl[1] = __halves2half2(lz, lw);
    }
}

// =====================================================================
// K2: x[65536,128] = P @ W via mma.sync fp16 3-term split
// CTA 128x128, 8 warps (4m x 2n), k-chunk 32, reg-prefetch pipeline.
// =====================================================================
constexpr int SA = 40;    // A smem stride in halfs (80B: conflict-free ldmatrix)
constexpr int SB = 136;   // B smem stride in halfs (272B: conflict-free .trans)

__global__ __launch_bounds__(256) void k2_gemm_mma(float* __restrict__ out)
{
    __shared__ __half sAh[128 * SA], sAl[128 * SA];
    __shared__ __half sBh[32 * SB],  sBl[32 * SB];

    const int tid  = threadIdx.x;
    const int lane = tid & 31, warp = tid >> 5;
    const int warp_m = warp & 3;          // 4 warps over M (32 rows each)
    const int warp_n = warp >> 2;         // 2 warps over N (64 cols each)
    const size_t rowBase = (size_t)blockIdx.x * 128;

    float acc[2][8][4];
    #pragma unroll
    for (int mt = 0; mt < 2; mt++)
        #pragma unroll
        for (int nt = 0; nt < 8; nt++)
            #pragma unroll
            for (int e = 0; e < 4; e++) acc[mt][nt][e] = 0.0f;

    // prefetch registers (chunk 0)
    uint4 pah[2], pal[2], pbh[2], pbl[2];
    {
        #pragma unroll
        for (int p = 0; p < 2; p++) {
            const int idx = p * 256 + tid;
            const int row = idx >> 2, c = idx & 3;      // A: 128 rows x 4 u4-cols
            const size_t go = (rowBase + row) * RDIM + c * 8;
            pah[p] = *reinterpret_cast<const uint4*>(g_Ph + go);
            pal[p] = *reinterpret_cast<const uint4*>(g_Pl + go);
            const int brow = idx >> 4, bc = idx & 15;   // B: 32 rows x 16 u4-cols
            const size_t gb = (size_t)brow * OUT_F + bc * 8;
            pbh[p] = *reinterpret_cast<const uint4*>(g_Whh + gb);
            pbl[p] = *reinterpret_cast<const uint4*>(g_Whl + gb);
        }
    }

    const uint32_t aAh = smem_u32(sAh), aAl = smem_u32(sAl);
    const uint32_t aBh = smem_u32(sBh), aBl = smem_u32(sBl);

    for (int t = 0; t < RDIM / 32; t++) {
        // commit prefetched chunk to smem
        #pragma unroll
        for (int p = 0; p < 2; p++) {
            const int idx = p * 256 + tid;
            const int row = idx >> 2, c = idx & 3;
            *reinterpret_cast<uint4*>(sAh + row * SA + c * 8) = pah[p];
            *reinterpret_cast<uint4*>(sAl + row * SA + c * 8) = pal[p];
            const int brow = idx >> 4, bc = idx & 15;
            *reinterpret_cast<uint4*>(sBh + brow * SB + bc * 8) = pbh[p];
            *reinterpret_cast<uint4*>(sBl + brow * SB + bc * 8) = pbl[p];
        }
        __syncthreads();

        // prefetch next chunk while mma runs
        if (t < RDIM / 32 - 1) {
            const int kn = (t + 1) * 32;
            #pragma unroll
            for (int p = 0; p < 2; p++) {
                const int idx = p * 256 + tid;
                const int row = idx >> 2, c = idx & 3;
                const size_t go = (rowBase + row) * RDIM + kn + c * 8;
                pah[p] = *reinterpret_cast<const uint4*>(g_Ph + go);
                pal[p] = *reinterpret_cast<const uint4*>(g_Pl + go);
                const int brow = idx >> 4, bc = idx & 15;
                const size_t gb = (size_t)(kn + brow) * OUT_F + bc * 8;
                pbh[p] = *reinterpret_cast<const uint4*>(g_Whh + gb);
                pbl[p] = *reinterpret_cast<const uint4*>(g_Whl + gb);
            }
        }

        #pragma unroll
        for (int ks = 0; ks < 32; ks += 16) {
            uint32_t Afh[2][4], Afl[2][4];
            #pragma unroll
            for (int mt = 0; mt < 2; mt++) {
                const int r = warp_m * 32 + mt * 16 + (lane & 15);
                const int col = ks + ((lane >> 4) << 3);
                const uint32_t off = (uint32_t)(r * SA + col) * 2;
                ldmatrix_x4(Afh[mt], aAh + off);
                ldmatrix_x4(Afl[mt], aAl + off);
            }
            uint32_t Bfh[4][4], Bfl[4][4];
            #pragma unroll
            for (int g = 0; g < 4; g++) {
                const int kr = ks + (lane & 15);
                const int nc = warp_n * 64 + g * 16 + ((lane >> 4) << 3);
                const uint32_t off = (uint32_t)(kr * SB + nc) * 2;
                ldmatrix_x4_t(Bfh[g], aBh + off);
                ldmatrix_x4_t(Bfl[g], aBl + off);
            }
            #pragma unroll
            for (int mt = 0; mt < 2; mt++) {
                #pragma unroll
                for (int g = 0; g < 4; g++) {
                    // hi*hi
                    mma16816(acc[mt][2 * g],     Afh[mt], &Bfh[g][0]);
                    mma16816(acc[mt][2 * g + 1], Afh[mt], &Bfh[g][2]);
                    // hi*lo
                    mma16816(acc[mt][2 * g],     Afh[mt], &Bfl[g][0]);
                    mma16816(acc[mt][2 * g + 1], Afh[mt], &Bfl[g][2]);
                    // lo*hi
                    mma16816(acc[mt][2 * g],     Afl[mt], &Bfh[g][0]);
                    mma16816(acc[mt][2 * g + 1], Afl[mt], &Bfh[g][2]);
                }
            }
        }
        __syncthreads();
    }

    // epilogue: direct float2 stores
    #pragma unroll
    for (int mt = 0; mt < 2; mt++) {
        const int r0 = (int)rowBase + warp_m * 32 + mt * 16 + (lane >> 2);
        #pragma unroll
        for (int nt = 0; nt < 8; nt++) {
            const int c0 = warp_n * 64 + nt * 8 + (lane & 3) * 2;
            *reinterpret_cast<float2*>(out + (size_t)r0 * OUT_F + c0) =
                make_float2(acc[mt][nt][0], acc[mt][nt][1]);
            *reinterpret_cast<float2*>(out + (size_t)(r0 + 8) * OUT_F + c0) =
                make_float2(acc[mt][nt][2], acc[mt][nt][3]);
        }
    }
}

// =====================================================================
// K3a: per-block partial column sums / sumsq over 256-row slices
// =====================================================================
__global__ __launch_bounds__(256) void k3a_partial(const float* __restrict__ x)
{
    const int t = threadIdx.x;
    const int c = t & 127, h = t >> 7;
    float s = 0.0f, q = 0.0f;
    const size_t rowBase = (size_t)blockIdx.x * 256;
    for (int r = 0; r < 128; r++) {
        const float v = x[(rowBase + (size_t)r * 2 + h) * OUT_F + c];
        s += v;
        q = fmaf(v, v, q);
    }
    __shared__ float ss[256], sq[256];
    ss[t] = s; sq[t] = q;
    __syncthreads();
    if (t < 128) {
        g_psum[blockIdx.x * OUT_F + t] = ss[t] + ss[t + 128];
        g_psq [blockIdx.x * OUT_F + t] = sq[t] + sq[t + 128];
    }
}

// K3b: parallel finalize — one CTA per column
__global__ __launch_bounds__(256) void k3b_finalize(const float* __restrict__ gamma,
                                                    const float* __restrict__ beta)
{
    __shared__ float ss[256], qq[256];
    const int c = blockIdx.x;      // 128 blocks
    const int t = threadIdx.x;     // 256 threads
    ss[t] = g_psum[t * OUT_F + c];
    qq[t] = g_psq [t * OUT_F + c];
    __syncthreads();
    #pragma unroll
    for (int stp = 128; stp > 0; stp >>= 1) {
        if (t < stp) { ss[t] += ss[t + stp]; qq[t] += qq[t + stp]; }
        __syncthreads();
    }
    if (t == 0) {
        const float inv_n = 1.0f / (float)N_PTS;
        const float mean = ss[0] * inv_n;
        const float var  = qq[0] * inv_n - mean * mean;
        const float sc   = gamma[c] * rsqrtf(var + BN_EPS);
        g_scale[c] = sc;
        g_bias[c]  = beta[c] - mean * sc;
    }
}

// K4: in-place BN affine + LeakyReLU
__global__ __launch_bounds__(256) void k4_bnrelu(float* __restrict__ x)
{
    const int i = blockIdx.x * 256 + threadIdx.x;
    float4 v = reinterpret_cast<float4*>(x)[i];
    const int c0 = (i * 4) & 127;
    const float4 sc = *reinterpret_cast<const float4*>(g_scale + c0);
    const float4 bi = *reinterpret_cast<const float4*>(g_bias + c0);
    v.x = fmaf(v.x, sc.x, bi.x); v.x = (v.x >= 0.0f) ? v.x : NEG_SLOPE * v.x;
    v.y = fmaf(v.y, sc.y, bi.y); v.y = (v.y >= 0.0f) ? v.y : NEG_SLOPE * v.y;
    v.z = fmaf(v.z, sc.z, bi.z); v.z = (v.z >= 0.0f) ? v.z : NEG_SLOPE * v.z;
    v.w = fmaf(v.w, sc.w, bi.w); v.w = (v.w >= 0.0f) ? v.w : NEG_SLOPE * v.w;
    reinterpret_cast<float4*>(x)[i] = v;
}

// =====================================================================
extern "C" void kernel_launch(void* const* d_in, const int* in_sizes, int n_in,
                              void* d_out, int out_size)
{
    const float* qp    = (const float*)d_in[0];
    const float* sp    = (const float*)d_in[1];
    const int*   nbr   = (const int*)  d_in[2];
    const float* feat  = (const float*)d_in[3];
    const float* kpts  = (const float*)d_in[4];
    const float* Wf    = (const float*)d_in[5];
    const float* gamma = (const float*)d_in[6];
    const float* beta  = (const float*)d_in[7];
    float* out = (float*)d_out;

    k0_prep<<<(RDIM * OUT_F + 255) / 256, 256>>>(Wf);
    k1_weighted<<<N_PTS / 16, 256>>>(qp, sp, nbr, feat, kpts);
    k2_gemm_mma<<<N_PTS / 128, 256>>>(out);
    k3a_partial<<<256, 256>>>(out);
    k3b_finalize<<<OUT_F, 256>>>(gamma, beta);
    k4_bnrelu<<<(N_PTS * OUT_F / 4) / 256, 256>>>(out);
}